// round 16
// baseline (speedup 1.0000x reference)
#include <cuda_runtime.h>
#include <cuda_bf16.h>
#include <math.h>
#include <stdint.h>

// ---------------------------------------------------------------------------
// MixMobileBlock on GB300: GEMMs via portable mma.sync tf32 (HMMA), fp32 accum.
// R15: 4-stage cp.async pipeline (BK=16, pitch 24, wait_group 2) => 3 iters of
//      fill slack; keeps R14's proj-fold + fused final residual epilogue.
// B=32, C=512, H=W=32, NH=8, dh=64, pooled N=256, MLP hidden=2048
// ---------------------------------------------------------------------------

namespace {
constexpr int Bc = 32, Ch = 512, NHn = 8;
constexpr int NT = 256;              // pooled tokens per image
constexpr int M1 = Bc * NT;          // 8192
constexpr int M2 = Bc * 32 * 32;     // 32768
}

// scratch: single device global (no runtime allocation allowed)
__device__ float g_s[167772160];

// float-offsets into g_s
constexpr size_t OFF_T0   = 0;             // [8192,512]
constexpr size_t OFF_TLN  = 4194304;       // [8192,512]   (K-permuted)
constexpr size_t OFF_QKV  = 8388608;       // [8192,1536]
constexpr size_t OFF_AO   = 20971520;      // [8192,512]   (K-permuted)
constexpr size_t OFF_WC   = 25165824;      // [2048,512]   combined convT weight
constexpr size_t OFF_BC   = 26214400;      // [2048]       combined convT bias
constexpr size_t OFF_G    = 29360128;      // [8192,2048]  (pq-major columns)
constexpr size_t OFF_LN2  = 62914560;      // [32768,512]  (K-permuted)
constexpr size_t OFF_HID  = 79691776;      // [32768,2048] (K-permuted)
constexpr size_t OFF_WQKV = 163577856;     // [1536,512]   (K-permuted)
constexpr size_t OFF_PWT  = 164364288;     // [512,512]    projw^T (K-permuted)
constexpr size_t OFF_WCT  = 164626432;     // [2048,512]   (K-permuted, pq-major)
constexpr size_t OFF_WPW1 = 165675008;     // [2048,512]   (K-permuted)
constexpr size_t OFF_WPW2 = 166723584;     // [512,2048]   (K-permuted)

// ======================= small helpers =====================================
__device__ __forceinline__ uint32_t smem_u32(const void* p) {
    uint32_t a;
    asm("{ .reg .u64 t; cvta.to.shared.u64 t, %1; cvt.u32.u64 %0, t; }"
        : "=r"(a) : "l"(p));
    return a;
}
__device__ __forceinline__ void cpasync16(uint32_t saddr, const void* gaddr) {
    asm volatile("cp.async.cg.shared.global [%0], [%1], 16;"
                 :: "r"(saddr), "l"(gaddr) : "memory");
}
__device__ __forceinline__ float rna_tf32(float x) {
    uint32_t u;
    asm("cvt.rna.tf32.f32 %0, %1;" : "=r"(u) : "f"(x));
    return __uint_as_float(u);
}
__device__ __forceinline__ void mma_tf32(float* c, const uint32_t* a, const uint32_t* b) {
    asm volatile("mma.sync.aligned.m16n8k8.row.col.f32.tf32.tf32.f32 "
                 "{%0,%1,%2,%3}, {%4,%5,%6,%7}, {%8,%9}, {%0,%1,%2,%3};"
                 : "+f"(c[0]), "+f"(c[1]), "+f"(c[2]), "+f"(c[3])
                 : "r"(a[0]), "r"(a[1]), "r"(a[2]), "r"(a[3]), "r"(b[0]), "r"(b[1]));
}
// K-permutation: within each block of 8, order [0,4,1,5,2,6,3,7].
__device__ __forceinline__ int kperm(int i) {
    return (i & ~7) | ((i & 3) << 1) | ((i >> 2) & 1);
}
__device__ __forceinline__ size_t kperm64(size_t i) {
    return (i & ~(size_t)7) | ((i & 3) << 1) | ((i >> 2) & 1);
}

// ======================= tf32 HMMA GEMM (4-stage pipeline) ==================
// out[M,N] = epi(A[M,K] @ B[N,K]^T + bias) * alpha ; optional GELU, optional
// tf32-round + K-permute of the output. If fout != nullptr: stage the tile in
// smem and write fout[b,c,pix] = tile + resid (transposed, coalesced).
// 128x128 tile, BK=16, 256 threads, 8 warps (4m x 2n, 32x64 each).
// 4 smem stages, one commit per iter, wait_group 2 => 3 iters of fill slack.
constexpr int BKP = 24;   // pitch: g*24 mod 32 = {0,24,16,8}; LDS.64 pairs
                          // {base+2tg, +1} tile all 32 banks per 16-lane phase
constexpr int STGF = 128 * BKP;                  // 3072 floats per matrix-stage
constexpr int NSTG = 4;
constexpr int GSMEM = 2 * NSTG * STGF * 4;       // 98304 bytes dynamic
constexpr int TP = 132;   // epilogue transpose pitch (conflict-free)

__global__ __launch_bounds__(256, 2) void gemm_tf32(
    const float* __restrict__ A, const float* __restrict__ B,
    const float* __restrict__ bias, float* __restrict__ out,
    int M, int N, int K, float alpha, int gelu, int rnd,
    const float* __restrict__ resid, float* __restrict__ fout)
{
    extern __shared__ float smem[];
    const uint32_t sbase = smem_u32(smem);
    const uint32_t sA0 = sbase;                       // 4 A stages
    const uint32_t sB0 = sbase + NSTG * STGF * 4;     // 4 B stages
    const int tid = threadIdx.x;
    const int bm = blockIdx.y * 128, bn = blockIdx.x * 128;

    // global->smem: 128 rows x 16 cols per stage; thread: rows lrow, lrow+64,
    // 16B at col lcol.
    const int lrow = tid >> 2;          // 0..63
    const int lcol = (tid & 3) * 4;     // 0..12
    const float* gA = A + (size_t)(bm + lrow) * K + lcol;
    const float* gB = B + (size_t)(bn + lrow) * K + lcol;
    const uint32_t stOff = (uint32_t)(lrow * BKP + lcol) * 4u;

    const int w = tid >> 5, lane = tid & 31;
    const int wm = (w & 3) * 32;    // warp m offset
    const int wn = (w >> 2) * 64;   // warp n offset
    const int g  = lane >> 2, tg = lane & 3;

    float acc[2][8][4];
#pragma unroll
    for (int i = 0; i < 2; i++)
#pragma unroll
    for (int j = 0; j < 8; j++)
#pragma unroll
    for (int q = 0; q < 4; q++) acc[i][j][q] = 0.f;

    const int C = K >> 4;

    // prologue: fill stages 0..2
#pragma unroll
    for (int s = 0; s < NSTG - 1; s++) {
        const int k0 = s * 16;
        cpasync16(sA0 + s * STGF * 4 + stOff, gA + k0);
        cpasync16(sA0 + s * STGF * 4 + stOff + 64 * BKP * 4,
                  gA + (size_t)64 * K + k0);
        cpasync16(sB0 + s * STGF * 4 + stOff, gB + k0);
        cpasync16(sB0 + s * STGF * 4 + stOff + 64 * BKP * 4,
                  gB + (size_t)64 * K + k0);
        asm volatile("cp.async.commit_group;" ::: "memory");
    }

    for (int c = 0; c < C; c++) {
        const int st = c & 3;
        // wait for stage c's fill (tail-decreasing group count)
        if (c + 3 <= C) {
            asm volatile("cp.async.wait_group 2;" ::: "memory");
        } else if (c + 2 == C) {
            asm volatile("cp.async.wait_group 1;" ::: "memory");
        } else {
            asm volatile("cp.async.wait_group 0;" ::: "memory");
        }
        __syncthreads();
        // fill stage (c+3)%4 == stage (c-1)%4, consumed before the barrier
        if (c + 3 < C) {
            const int ns = (c + 3) & 3;
            const int k0 = (c + 3) * 16;
            cpasync16(sA0 + ns * STGF * 4 + stOff, gA + k0);
            cpasync16(sA0 + ns * STGF * 4 + stOff + 64 * BKP * 4,
                      gA + (size_t)64 * K + k0);
            cpasync16(sB0 + ns * STGF * 4 + stOff, gB + k0);
            cpasync16(sB0 + ns * STGF * 4 + stOff + 64 * BKP * 4,
                      gB + (size_t)64 * K + k0);
            asm volatile("cp.async.commit_group;" ::: "memory");
        }

        const uint32_t* sa = (const uint32_t*)(smem + st * STGF);
        const uint32_t* sb = (const uint32_t*)(smem + NSTG * STGF + st * STGF);
#pragma unroll
        for (int ks = 0; ks < 2; ks++) {
            const int k0 = ks * 8;
            // permuted layout: (orig tg, orig tg+4) adjacent at k0 + 2*tg
            uint32_t a[2][4];
#pragma unroll
            for (int mi = 0; mi < 2; mi++) {
                const int r0 = wm + mi * 16 + g;
                uint2 v0 = *(const uint2*)(sa + (r0)     * BKP + k0 + 2 * tg);
                uint2 v1 = *(const uint2*)(sa + (r0 + 8) * BKP + k0 + 2 * tg);
                a[mi][0] = v0.x; a[mi][2] = v0.y;
                a[mi][1] = v1.x; a[mi][3] = v1.y;
            }
            uint32_t b[8][2];
#pragma unroll
            for (int nj = 0; nj < 8; nj++) {
                const int rn = wn + nj * 8 + g;
                uint2 bv = *(const uint2*)(sb + rn * BKP + k0 + 2 * tg);
                b[nj][0] = bv.x; b[nj][1] = bv.y;
            }
#pragma unroll
            for (int mi = 0; mi < 2; mi++)
#pragma unroll
            for (int nj = 0; nj < 8; nj++)
                mma_tf32(acc[mi][nj], a[mi], b[nj]);
        }
    }

    if (fout) __syncthreads();   // smem reuse for transpose staging

    // epilogue
#pragma unroll
    for (int mi = 0; mi < 2; mi++) {
#pragma unroll
        for (int part = 0; part < 2; part++) {
            const int rl = wm + mi * 16 + part * 8 + g;
            const size_t row = (size_t)(bm + rl);
#pragma unroll
            for (int nj = 0; nj < 8; nj++) {
                const int cl = wn + nj * 8 + tg * 2;
                const int col = bn + cl;
                float v0 = acc[mi][nj][part * 2 + 0];
                float v1 = acc[mi][nj][part * 2 + 1];
                if (bias) { v0 += __ldg(&bias[col]); v1 += __ldg(&bias[col + 1]); }
                v0 *= alpha; v1 *= alpha;
                if (gelu) {
                    v0 = 0.5f * v0 * (1.0f + erff(v0 * 0.7071067811865476f));
                    v1 = 0.5f * v1 * (1.0f + erff(v1 * 0.7071067811865476f));
                }
                if (fout) {
                    smem[cl * TP + rl]       = v0;
                    smem[(cl + 1) * TP + rl] = v1;
                } else if (rnd) {
                    out[row * (size_t)N + kperm(col)]     = rna_tf32(v0);
                    out[row * (size_t)N + kperm(col + 1)] = rna_tf32(v1);
                } else {
                    *(float2*)(out + row * (size_t)N + col) = make_float2(v0, v1);
                }
            }
        }
    }

    if (fout) {
        __syncthreads();
        const int b = bm >> 10;          // 1024 pixels per image
        const int pix0 = bm & 1023;
#pragma unroll
        for (int i = 0; i < 16; i++) {
            const int cl = w * 16 + i;
            const size_t gb = ((size_t)b * 512 + bn + cl) * 1024 + pix0 + lane * 4;
            float4 tv = *(float4*)&smem[cl * TP + lane * 4];
            float4 iv = *(const float4*)(resid + gb);
            *(float4*)(fout + gb) =
                make_float4(tv.x + iv.x, tv.y + iv.y, tv.z + iv.z, tv.w + iv.w);
        }
    }
}

// ======================= elementwise kernels ===============================
// fp32 -> tf32-rounded fp32 weights, K-permuted layout (row stride % 8 == 0)
__global__ void k_cvt(const float* __restrict__ in, float* __restrict__ out, int n)
{
    int i = blockIdx.x * 256 + threadIdx.x;
    if (i < n) out[kperm(i)] = rna_tf32(in[i]);
}

// projw^T, tf32-rounded, K-permuted over j: pwt[kperm(k*512+j)] = projw[j][k]
__global__ void k_pwt(const float* __restrict__ projw, float* __restrict__ pwt)
{
    int idx = blockIdx.x * 256 + threadIdx.x;   // over 512*512
    int k = idx >> 9, j = idx & 511;
    pwt[kperm(idx)] = rna_tf32(projw[(size_t)j * 512 + k]);
}

// combined convT bias: bc[n'=pq*512+o] = 2 * sum_j projb[j] * ctw[j][o][p][q]
__global__ void k_bc(const float* __restrict__ ctw, const float* __restrict__ projb,
                     float* __restrict__ bc)
{
    int n = blockIdx.x;              // 2048
    int pq = n >> 9, o = n & 511;
    int p = pq >> 1, q = pq & 1;
    int t = threadIdx.x;             // 256
    float s = 0.f;
    for (int j = t; j < 512; j += 256)
        s += projb[j] * ctw[(((size_t)j * 512 + o) * 2 + p) * 2 + q];
#pragma unroll
    for (int off = 16; off > 0; off >>= 1)
        s += __shfl_xor_sync(0xffffffffu, s, off);
    __shared__ float sm[8];
    if ((t & 31) == 0) sm[t >> 5] = s;
    __syncthreads();
    if (t == 0) {
        float S = 0.f;
#pragma unroll
        for (int i = 0; i < 8; i++) S += sm[i];
        bc[n] = 2.f * S;
    }
}

// depthwise 3x3 conv (+bias) + residual + 2x2 avgpool -> fp32 tokens
__global__ void k_dwpool(const float* __restrict__ x, const float* __restrict__ dww,
                         const float* __restrict__ dwb, float* __restrict__ t0)
{
    int bc = blockIdx.x;
    int c = bc & (Ch - 1);
    int b = bc >> 9;
    __shared__ float tile[32][33];
    const float* xp = x + (size_t)bc * 1024;
    for (int i = threadIdx.x; i < 1024; i += 256)
        tile[i >> 5][i & 31] = xp[i];
    float w[9];
#pragma unroll
    for (int i = 0; i < 9; i++) w[i] = dww[c * 9 + i];
    float bb = dwb[c];
    __syncthreads();
    int pi = threadIdx.x >> 4, pj = threadIdx.x & 15;
    float s = 0.f;
#pragma unroll
    for (int di = 0; di < 2; di++)
#pragma unroll
    for (int dj = 0; dj < 2; dj++) {
        int y = pi * 2 + di, xx = pj * 2 + dj;
        float a = bb + tile[y][xx];
#pragma unroll
        for (int u = 0; u < 3; u++)
#pragma unroll
        for (int v = 0; v < 3; v++) {
            int yy = y + u - 1, xc = xx + v - 1;
            if (yy >= 0 && yy < 32 && xc >= 0 && xc < 32)
                a += tile[yy][xc] * w[u * 3 + v];
        }
        s += a;
    }
    t0[((size_t)b * NT + pi * 16 + pj) * Ch + c] = 0.25f * s;
}

// LayerNorm over 512, fp32 in -> tf32-rounded, K-PERMUTED fp32 out
__global__ void k_ln512(const float* __restrict__ in, float* __restrict__ out,
                        const float* __restrict__ g, const float* __restrict__ beta)
{
    int row = blockIdx.x, t = threadIdx.x;
    float2 v = ((const float2*)(in + (size_t)row * Ch))[t];
    float s = v.x + v.y, q = v.x * v.x + v.y * v.y;
#pragma unroll
    for (int o = 16; o > 0; o >>= 1) {
        s += __shfl_xor_sync(0xffffffffu, s, o);
        q += __shfl_xor_sync(0xffffffffu, q, o);
    }
    __shared__ float ssm[8], qsm[8];
    if ((t & 31) == 0) { ssm[t >> 5] = s; qsm[t >> 5] = q; }
    __syncthreads();
    float S = 0.f, Q = 0.f;
#pragma unroll
    for (int i = 0; i < 8; i++) { S += ssm[i]; Q += qsm[i]; }
    float mean = S * (1.f / Ch);
    float inv = rsqrtf(Q * (1.f / Ch) - mean * mean + 1e-6f);
    float2 gg = ((const float2*)g)[t];
    float2 bb = ((const float2*)beta)[t];
    float* orow = out + (size_t)row * Ch;
    orow[kperm(2 * t)]     = rna_tf32((v.x - mean) * inv * gg.x + bb.x);
    orow[kperm(2 * t + 1)] = rna_tf32((v.y - mean) * inv * gg.y + bb.y);
}

// Fused: gather convT-GEMM row (+ct_b) -> LN -> tf32-rounded K-PERMUTED out.
// G columns are pq-major (n' = pq*512 + o) => this read is fully contiguous.
__global__ void k_scln(const float* __restrict__ G, const float* __restrict__ ctb,
                       float* __restrict__ out,
                       const float* __restrict__ g, const float* __restrict__ beta)
{
    int row = blockIdx.x, t = threadIdx.x;
    int xg = row & 31;
    int yg = (row >> 5) & 31;
    int b  = row >> 10;
    int i = yg >> 1, p = yg & 1, j = xg >> 1, q = xg & 1;
    const int pq = p * 2 + q;
    const float* gr = G + (size_t)(b * 256 + i * 16 + j) * 2048 + pq * 512;
    const int c0 = 2 * t;
    float2 cb = ((const float2*)ctb)[t];
    float2 gv = ((const float2*)gr)[t];     // contiguous, coalesced
    float2 v;
    v.x = gv.x + cb.x;
    v.y = gv.y + cb.y;

    float s = v.x + v.y, qq = v.x * v.x + v.y * v.y;
#pragma unroll
    for (int o = 16; o > 0; o >>= 1) {
        s  += __shfl_xor_sync(0xffffffffu, s, o);
        qq += __shfl_xor_sync(0xffffffffu, qq, o);
    }
    __shared__ float ssm[8], qsm[8];
    if ((t & 31) == 0) { ssm[t >> 5] = s; qsm[t >> 5] = qq; }
    __syncthreads();
    float S = 0.f, Q = 0.f;
#pragma unroll
    for (int k = 0; k < 8; k++) { S += ssm[k]; Q += qsm[k]; }
    float mean = S * (1.f / Ch);
    float inv = rsqrtf(Q * (1.f / Ch) - mean * mean + 1e-6f);
    float2 gg = ((const float2*)g)[t];
    float2 bb = ((const float2*)beta)[t];
    float* orow = out + (size_t)row * Ch;
    orow[kperm(c0)]     = rna_tf32((v.x - mean) * inv * gg.x + bb.x);
    orow[kperm(c0 + 1)] = rna_tf32((v.y - mean) * inv * gg.y + bb.y);
}

// XCA attention (fp32 in, tf32-rounded K-PERMUTED fp32 out)
__global__ void k_attn(const float* __restrict__ qkv, const float* __restrict__ mask,
                       const float* __restrict__ temp, float* __restrict__ ao)
{
    extern __shared__ float sm[];
    float* qs  = sm;            // pitch 257
    float* ks  = sm + 16448;
    float* as_ = sm + 32896;    // pitch 65
    int bh = blockIdx.x;
    int h = bh & 7, b = bh >> 3;
    int t = threadIdx.x;
    const float* base = qkv + (size_t)b * NT * 1536 + h * 64;

    for (int idx = t; idx < 64 * 256; idx += 256) {
        int d = idx & 63, n = idx >> 6;
        qs[d * 257 + n] = base[(size_t)n * 1536 + d];
        ks[d * 257 + n] = base[(size_t)n * 1536 + 512 + d];
    }
    __syncthreads();

    float tmp = temp[h];
    {
        int r = t >> 2, s4 = t & 3;
        float sq = 0.f, sk = 0.f;
        for (int n = s4 * 64; n < s4 * 64 + 64; n++) {
            float a = qs[r * 257 + n]; sq += a * a;
            float c = ks[r * 257 + n]; sk += c * c;
        }
        sq += __shfl_xor_sync(0xffffffffu, sq, 1);
        sq += __shfl_xor_sync(0xffffffffu, sq, 2);
        sk += __shfl_xor_sync(0xffffffffu, sk, 1);
        sk += __shfl_xor_sync(0xffffffffu, sk, 2);
        float qsc = tmp / fmaxf(sqrtf(sq), 1e-12f);
        float ksc = 1.f / fmaxf(sqrtf(sk), 1e-12f);
        for (int n = s4 * 64; n < s4 * 64 + 64; n++) {
            qs[r * 257 + n] *= qsc;
            ks[r * 257 + n] *= ksc;
        }
    }
    __syncthreads();

    {
        int d = t >> 2, s4 = t & 3;
        float vals[16];
#pragma unroll
        for (int i = 0; i < 16; i++) vals[i] = 0.f;
        for (int n = 0; n < 256; n++) {
            float qv = qs[d * 257 + n];
#pragma unroll
            for (int i = 0; i < 16; i++)
                vals[i] += qv * ks[(s4 * 16 + i) * 257 + n];
        }
#pragma unroll
        for (int i = 0; i < 16; i++) {
            int e = s4 * 16 + i;
            float mu = mask[(((size_t)b * 8 + h) * 64 + d) * 64 + e];
            if (mu < 0.2f) vals[i] += -1e12f;
        }
        float mx = vals[0];
#pragma unroll
        for (int i = 1; i < 16; i++) mx = fmaxf(mx, vals[i]);
        mx = fmaxf(mx, __shfl_xor_sync(0xffffffffu, mx, 1));
        mx = fmaxf(mx, __shfl_xor_sync(0xffffffffu, mx, 2));
        float sum = 0.f;
#pragma unroll
        for (int i = 0; i < 16; i++) { vals[i] = expf(vals[i] - mx); sum += vals[i]; }
        sum += __shfl_xor_sync(0xffffffffu, sum, 1);
        sum += __shfl_xor_sync(0xffffffffu, sum, 2);
        float isum = 1.f / sum;
#pragma unroll
        for (int i = 0; i < 16; i++) as_[d * 65 + s4 * 16 + i] = vals[i] * isum;
    }
    __syncthreads();

    for (int idx = t; idx < 64 * 256; idx += 256) {
        int d = idx & 63, n = idx >> 6;
        qs[d * 257 + n] = base[(size_t)n * 1536 + 1024 + d];
    }
    __syncthreads();

    {
        int d0 = (t >> 4) * 4, n0 = (t & 15) * 16;
        float acc[4][16];
#pragma unroll
        for (int i = 0; i < 4; i++)
#pragma unroll
        for (int j = 0; j < 16; j++) acc[i][j] = 0.f;
        for (int e = 0; e < 64; e++) {
            float a0 = as_[(d0 + 0) * 65 + e];
            float a1 = as_[(d0 + 1) * 65 + e];
            float a2 = as_[(d0 + 2) * 65 + e];
            float a3 = as_[(d0 + 3) * 65 + e];
#pragma unroll
            for (int j = 0; j < 16; j++) {
                float vv = qs[e * 257 + n0 + j];
                acc[0][j] += a0 * vv;
                acc[1][j] += a1 * vv;
                acc[2][j] += a2 * vv;
                acc[3][j] += a3 * vv;
            }
        }
        float* aop = ao + (size_t)b * NT * Ch + h * 64;
#pragma unroll
        for (int i = 0; i < 4; i++)
#pragma unroll
        for (int j = 0; j < 16; j++)
            aop[kperm64((size_t)(n0 + j) * Ch + d0 + i)] = rna_tf32(acc[i][j]);
    }
}

// convT weight reshape, pq-major columns: Wct[pq*512 + o][perm(c)] =
// ct_w[c][o][p][q], tf32-rounded. (A-side of the weight-fold GEMM.)
__global__ void k_wct(const float* __restrict__ ctw, float* __restrict__ wct)
{
    int idx = blockIdx.x * 256 + threadIdx.x;   // over 2048*512 output elems
    int cI = idx & 511;
    int nI = idx >> 9;          // n' = pq*512 + o
    int pq = nI >> 9;
    int o  = nI & 511;
    int p = pq >> 1, q = pq & 1;
    wct[kperm(idx)] = rna_tf32(ctw[(((size_t)cI * 512 + o) * 2 + p) * 2 + q]);
}

// ===========================================================================
extern "C" void kernel_launch(void* const* d_in, const int* in_sizes, int n_in,
                              void* d_out, int out_size)
{
    (void)in_sizes; (void)n_in; (void)out_size;
    const float* x     = (const float*)d_in[0];
    const float* mask  = (const float*)d_in[1];
    const float* dw_w  = (const float*)d_in[2];
    const float* dw_b  = (const float*)d_in[3];
    const float* ln1g  = (const float*)d_in[4];
    const float* ln1b  = (const float*)d_in[5];
    const float* qkvw  = (const float*)d_in[6];
    const float* qkvb  = (const float*)d_in[7];
    const float* temp  = (const float*)d_in[8];
    const float* projw = (const float*)d_in[9];
    const float* projb = (const float*)d_in[10];
    const float* ctw   = (const float*)d_in[11];
    const float* ctb   = (const float*)d_in[12];
    const float* ln2g  = (const float*)d_in[13];
    const float* ln2b  = (const float*)d_in[14];
    const float* pw1w  = (const float*)d_in[15];
    const float* pw1b  = (const float*)d_in[16];
    const float* pw2w  = (const float*)d_in[17];
    const float* pw2b  = (const float*)d_in[18];
    float* out = (float*)d_out;

    float* S = nullptr;
    cudaGetSymbolAddress((void**)&S, g_s);

    cudaFuncSetAttribute(k_attn, cudaFuncAttributeMaxDynamicSharedMemorySize, 148224);
    cudaFuncSetAttribute(gemm_tf32, cudaFuncAttributeMaxDynamicSharedMemorySize, GSMEM);

    // launch order puts the big GEMMs early for ncu visibility (-s 5 -c 1)
    k_cvt<<<(1536 * 512 + 255) / 256, 256>>>(qkvw, S + OFF_WQKV, 1536 * 512);   // 0
    k_dwpool<<<Bc * Ch, 256>>>(x, dw_w, dw_b, S + OFF_T0);                      // 1
    k_ln512<<<M1, 256>>>(S + OFF_T0, S + OFF_TLN, ln1g, ln1b);                  // 2

    // 3: qkv = LN1 @ qkv_w^T + qkv_b : [8192,1536] (feeds attention: no rnd)
    gemm_tf32<<<dim3(1536 / 128, M1 / 128), 256, GSMEM>>>(
        S + OFF_TLN, S + OFF_WQKV, qkvb, S + OFF_QKV, M1, 1536, 512, 1.f, 0, 0,
        nullptr, nullptr);

    // 4: XCA attention (tf32-rounded, K-permuted out)
    k_attn<<<Bc * NHn, 256, 148224>>>(S + OFF_QKV, mask, temp, S + OFF_AO);

    // weight-fold pipeline: Wc = 2 * Wct @ projw  (proj GEMM eliminated)
    k_wct<<<(2048 * 512) / 256, 256>>>(ctw, S + OFF_WCT);                       // 5
    k_pwt<<<(512 * 512) / 256, 256>>>(projw, S + OFF_PWT);                      // 6

    // 7: Wc[n,k] = 2 * sum_j Wct[n,j] projw[j,k]  (rnd+perm for main GEMM)
    gemm_tf32<<<dim3(512 / 128, 2048 / 128), 256, GSMEM>>>(
        S + OFF_WCT, S + OFF_PWT, nullptr, S + OFF_WC, 2048, 512, 512, 2.f, 0, 1,
        nullptr, nullptr);

    k_bc<<<2048, 256>>>(ctw, projb, S + OFF_BC);                                // 8

    // 9: G = AO @ Wc^T + bc : [8192,2048], pq-major columns
    gemm_tf32<<<dim3(2048 / 128, M1 / 128), 256, GSMEM>>>(
        S + OFF_AO, S + OFF_WC, S + OFF_BC, S + OFF_G, M1, 2048, 512, 1.f, 0, 0,
        nullptr, nullptr);

    // 10: fused scatter(+ct_b) + LN2 (coalesced gather, tf32-rounded out)
    k_scln<<<M2, 256>>>(S + OFF_G, ctb, S + OFF_LN2, ln2g, ln2b);

    k_cvt<<<(2048 * 512 + 255) / 256, 256>>>(pw1w, S + OFF_WPW1, 2048 * 512);   // 11

    // 12: MLP hidden = gelu(LN2 @ pw1^T + b1) (feeds pw2 GEMM: rnd+perm)
    gemm_tf32<<<dim3(2048 / 128, M2 / 128), 256, GSMEM>>>(
        S + OFF_LN2, S + OFF_WPW1, pw1b, S + OFF_HID, M2, 2048, 512, 1.f, 1, 1,
        nullptr, nullptr);

    k_cvt<<<(512 * 2048 + 255) / 256, 256>>>(pw2w, S + OFF_WPW2, 512 * 2048);   // 13

    // 14: MLP out = hidden @ pw2^T + b2, fused final residual + NCHW transpose
    gemm_tf32<<<dim3(512 / 128, M2 / 128), 256, GSMEM>>>(
        S + OFF_HID, S + OFF_WPW2, pw2b, nullptr, M2, 512, 2048, 1.f, 0, 0,
        x, out);
}

// round 17
// speedup vs baseline: 1.1313x; 1.1313x over previous
#include <cuda_runtime.h>
#include <cuda_bf16.h>
#include <math.h>
#include <stdint.h>

// ---------------------------------------------------------------------------
// MixMobileBlock on GB300: GEMMs via portable mma.sync tf32 (HMMA), fp32 accum.
// R16: R14 GEMM geometry restored (BK=32, pitch 40, 2 stages, 2 CTA/SM —
//      proven local optimum) + all weight-prep merged into ONE kernel.
// B=32, C=512, H=W=32, NH=8, dh=64, pooled N=256, MLP hidden=2048
// ---------------------------------------------------------------------------

namespace {
constexpr int Bc = 32, Ch = 512, NHn = 8;
constexpr int NT = 256;              // pooled tokens per image
constexpr int M1 = Bc * NT;          // 8192
constexpr int M2 = Bc * 32 * 32;     // 32768
}

// scratch: single device global (no runtime allocation allowed)
__device__ float g_s[167772160];

// float-offsets into g_s
constexpr size_t OFF_T0   = 0;             // [8192,512]
constexpr size_t OFF_TLN  = 4194304;       // [8192,512]   (K-permuted)
constexpr size_t OFF_QKV  = 8388608;       // [8192,1536]
constexpr size_t OFF_AO   = 20971520;      // [8192,512]   (K-permuted)
constexpr size_t OFF_WC   = 25165824;      // [2048,512]   combined convT weight
constexpr size_t OFF_BC   = 26214400;      // [2048]       combined convT bias
constexpr size_t OFF_G    = 29360128;      // [8192,2048]  (pq-major columns)
constexpr size_t OFF_LN2  = 62914560;      // [32768,512]  (K-permuted)
constexpr size_t OFF_HID  = 79691776;      // [32768,2048] (K-permuted)
constexpr size_t OFF_WQKV = 163577856;     // [1536,512]   (K-permuted)
constexpr size_t OFF_PWT  = 164364288;     // [512,512]    projw^T (K-permuted)
constexpr size_t OFF_WCT  = 164626432;     // [2048,512]   (K-permuted, pq-major)
constexpr size_t OFF_WPW1 = 165675008;     // [2048,512]   (K-permuted)
constexpr size_t OFF_WPW2 = 166723584;     // [512,2048]   (K-permuted)

// ======================= small helpers =====================================
__device__ __forceinline__ uint32_t smem_u32(const void* p) {
    uint32_t a;
    asm("{ .reg .u64 t; cvta.to.shared.u64 t, %1; cvt.u32.u64 %0, t; }"
        : "=r"(a) : "l"(p));
    return a;
}
__device__ __forceinline__ void cpasync16(uint32_t saddr, const void* gaddr) {
    asm volatile("cp.async.cg.shared.global [%0], [%1], 16;"
                 :: "r"(saddr), "l"(gaddr) : "memory");
}
__device__ __forceinline__ float rna_tf32(float x) {
    uint32_t u;
    asm("cvt.rna.tf32.f32 %0, %1;" : "=r"(u) : "f"(x));
    return __uint_as_float(u);
}
__device__ __forceinline__ void mma_tf32(float* c, const uint32_t* a, const uint32_t* b) {
    asm volatile("mma.sync.aligned.m16n8k8.row.col.f32.tf32.tf32.f32 "
                 "{%0,%1,%2,%3}, {%4,%5,%6,%7}, {%8,%9}, {%0,%1,%2,%3};"
                 : "+f"(c[0]), "+f"(c[1]), "+f"(c[2]), "+f"(c[3])
                 : "r"(a[0]), "r"(a[1]), "r"(a[2]), "r"(a[3]), "r"(b[0]), "r"(b[1]));
}
// K-permutation: within each block of 8, order [0,4,1,5,2,6,3,7].
__device__ __forceinline__ int kperm(int i) {
    return (i & ~7) | ((i & 3) << 1) | ((i >> 2) & 1);
}
__device__ __forceinline__ size_t kperm64(size_t i) {
    return (i & ~(size_t)7) | ((i & 3) << 1) | ((i >> 2) & 1);
}

// ======================= tf32 HMMA GEMM (R14 geometry) ======================
// out[M,N] = epi(A[M,K] @ B[N,K]^T + bias) * alpha ; optional GELU, optional
// tf32-round + K-permute of the output. If fout != nullptr: stage the tile in
// smem and write fout[b,c,pix] = tile + resid (transposed, coalesced).
// 128x128 tile, BK=32, 256 threads, 8 warps (4m x 2n, 32x64 each).
// ONE __syncthreads per mainloop iteration (cp.async issued post-barrier).
constexpr int BKP = 40;   // smem pitch: conflict-free LDS.64 fragment loads
constexpr int TILEF = 128 * BKP;                 // floats per tile
constexpr int GSMEM = 2 * 2 * TILEF * 4;         // 81920 bytes dynamic
constexpr int TP = 132;   // epilogue transpose pitch (conflict-free)

__global__ __launch_bounds__(256, 2) void gemm_tf32(
    const float* __restrict__ A, const float* __restrict__ B,
    const float* __restrict__ bias, float* __restrict__ out,
    int M, int N, int K, float alpha, int gelu, int rnd,
    const float* __restrict__ resid, float* __restrict__ fout)
{
    extern __shared__ float smem[];
    const uint32_t sbase = smem_u32(smem);
    const uint32_t sAb[2] = { sbase, sbase + TILEF * 4 };
    const uint32_t sBb[2] = { sbase + 2 * TILEF * 4, sbase + 3 * TILEF * 4 };
    const int tid = threadIdx.x;
    const int bm = blockIdx.y * 128, bn = blockIdx.x * 128;

    const int lrow = tid >> 3;          // 0..31
    const int lcol = (tid & 7) * 4;     // 0..28
    const float* gA = A + (size_t)(bm + lrow) * K + lcol;
    const float* gB = B + (size_t)(bn + lrow) * K + lcol;
    const uint32_t stOff = (uint32_t)(lrow * BKP + lcol) * 4u;

    const int w = tid >> 5, lane = tid & 31;
    const int wm = (w & 3) * 32;    // warp m offset
    const int wn = (w >> 2) * 64;   // warp n offset
    const int g  = lane >> 2, tg = lane & 3;

    float acc[2][8][4];
#pragma unroll
    for (int i = 0; i < 2; i++)
#pragma unroll
    for (int j = 0; j < 8; j++)
#pragma unroll
    for (int q = 0; q < 4; q++) acc[i][j][q] = 0.f;

    const int C = K >> 5;

    // preload chunk 0
#pragma unroll
    for (int r = 0; r < 4; r++) {
        cpasync16(sAb[0] + stOff + r * 32 * BKP * 4, gA + (size_t)(r * 32) * K);
        cpasync16(sBb[0] + stOff + r * 32 * BKP * 4, gB + (size_t)(r * 32) * K);
    }
    asm volatile("cp.async.commit_group;" ::: "memory");

    for (int c = 0; c < C; c++) {
        const int buf = c & 1;
        asm volatile("cp.async.wait_group 0;" ::: "memory");
        __syncthreads();
        if (c + 1 < C) {
            const int nb = (c + 1) & 1;
            const int k0 = (c + 1) * 32;
#pragma unroll
            for (int r = 0; r < 4; r++) {
                cpasync16(sAb[nb] + stOff + r * 32 * BKP * 4,
                          gA + (size_t)(r * 32) * K + k0);
                cpasync16(sBb[nb] + stOff + r * 32 * BKP * 4,
                          gB + (size_t)(r * 32) * K + k0);
            }
            asm volatile("cp.async.commit_group;" ::: "memory");
        }

        const uint32_t* sa = (const uint32_t*)(smem + (buf ? TILEF : 0));
        const uint32_t* sb = (const uint32_t*)(smem + 2 * TILEF + (buf ? TILEF : 0));
#pragma unroll
        for (int ks = 0; ks < 4; ks++) {
            const int k0 = ks * 8;
            uint32_t a[2][4];
#pragma unroll
            for (int mi = 0; mi < 2; mi++) {
                const int r0 = wm + mi * 16 + g;
                uint2 v0 = *(const uint2*)(sa + (r0)     * BKP + k0 + 2 * tg);
                uint2 v1 = *(const uint2*)(sa + (r0 + 8) * BKP + k0 + 2 * tg);
                a[mi][0] = v0.x; a[mi][2] = v0.y;
                a[mi][1] = v1.x; a[mi][3] = v1.y;
            }
            uint32_t b[8][2];
#pragma unroll
            for (int nj = 0; nj < 8; nj++) {
                const int rn = wn + nj * 8 + g;
                uint2 bv = *(const uint2*)(sb + rn * BKP + k0 + 2 * tg);
                b[nj][0] = bv.x; b[nj][1] = bv.y;
            }
#pragma unroll
            for (int mi = 0; mi < 2; mi++)
#pragma unroll
            for (int nj = 0; nj < 8; nj++)
                mma_tf32(acc[mi][nj], a[mi], b[nj]);
        }
    }

    if (fout) __syncthreads();   // smem reuse for transpose staging

    // epilogue
#pragma unroll
    for (int mi = 0; mi < 2; mi++) {
#pragma unroll
        for (int part = 0; part < 2; part++) {
            const int rl = wm + mi * 16 + part * 8 + g;
            const size_t row = (size_t)(bm + rl);
#pragma unroll
            for (int nj = 0; nj < 8; nj++) {
                const int cl = wn + nj * 8 + tg * 2;
                const int col = bn + cl;
                float v0 = acc[mi][nj][part * 2 + 0];
                float v1 = acc[mi][nj][part * 2 + 1];
                if (bias) { v0 += __ldg(&bias[col]); v1 += __ldg(&bias[col + 1]); }
                v0 *= alpha; v1 *= alpha;
                if (gelu) {
                    v0 = 0.5f * v0 * (1.0f + erff(v0 * 0.7071067811865476f));
                    v1 = 0.5f * v1 * (1.0f + erff(v1 * 0.7071067811865476f));
                }
                if (fout) {
                    smem[cl * TP + rl]       = v0;
                    smem[(cl + 1) * TP + rl] = v1;
                } else if (rnd) {
                    out[row * (size_t)N + kperm(col)]     = rna_tf32(v0);
                    out[row * (size_t)N + kperm(col + 1)] = rna_tf32(v1);
                } else {
                    *(float2*)(out + row * (size_t)N + col) = make_float2(v0, v1);
                }
            }
        }
    }

    if (fout) {
        __syncthreads();
        const int b = bm >> 10;          // 1024 pixels per image
        const int pix0 = bm & 1023;
#pragma unroll
        for (int i = 0; i < 16; i++) {
            const int cl = w * 16 + i;
            const size_t gb = ((size_t)b * 512 + bn + cl) * 1024 + pix0 + lane * 4;
            float4 tv = *(float4*)&smem[cl * TP + lane * 4];
            float4 iv = *(const float4*)(resid + gb);
            *(float4*)(fout + gb) =
                make_float4(tv.x + iv.x, tv.y + iv.y, tv.z + iv.z, tv.w + iv.w);
        }
    }
}

// ======================= elementwise kernels ===============================
// ONE merged weight-prep kernel: all tf32-rounded, K-permuted weight layouts.
// Regions (element counts):
//   [0, 786432)            WQKV[kperm(i)]  = rna(qkvw[i])
//   [786432, 1048576)      PWT[kperm(i')]  = rna(projw[j*512+k])  (transpose)
//   [1048576, 2097152)     WCT[kperm(i')]  = rna(ctw[...]) pq-major reshape
//   [2097152, 3145728)     WPW1[kperm(i')] = rna(pw1w[i'])
//   [3145728, 4194304)     WPW2[kperm(i')] = rna(pw2w[i'])
__global__ void k_wprep(const float* __restrict__ qkvw, const float* __restrict__ projw,
                        const float* __restrict__ ctw, const float* __restrict__ pw1w,
                        const float* __restrict__ pw2w, float* __restrict__ S)
{
    int i = blockIdx.x * 256 + threadIdx.x;     // 0 .. 4194303
    if (i < 786432) {
        (S + OFF_WQKV)[kperm(i)] = rna_tf32(qkvw[i]);
    } else if (i < 1048576) {
        int i2 = i - 786432;
        int k = i2 >> 9, j = i2 & 511;
        (S + OFF_PWT)[kperm(i2)] = rna_tf32(projw[(size_t)j * 512 + k]);
    } else if (i < 2097152) {
        int i2 = i - 1048576;
        int cI = i2 & 511;
        int nI = i2 >> 9;           // n' = pq*512 + o
        int pq = nI >> 9, o = nI & 511;
        int p = pq >> 1, q = pq & 1;
        (S + OFF_WCT)[kperm(i2)] = rna_tf32(ctw[(((size_t)cI * 512 + o) * 2 + p) * 2 + q]);
    } else if (i < 3145728) {
        int i2 = i - 2097152;
        (S + OFF_WPW1)[kperm(i2)] = rna_tf32(pw1w[i2]);
    } else {
        int i2 = i - 3145728;
        (S + OFF_WPW2)[kperm(i2)] = rna_tf32(pw2w[i2]);
    }
}

// combined convT bias: bc[n'=pq*512+o] = 2 * sum_j projb[j] * ctw[j][o][p][q]
__global__ void k_bc(const float* __restrict__ ctw, const float* __restrict__ projb,
                     float* __restrict__ bc)
{
    int n = blockIdx.x;              // 2048
    int pq = n >> 9, o = n & 511;
    int p = pq >> 1, q = pq & 1;
    int t = threadIdx.x;             // 256
    float s = 0.f;
    for (int j = t; j < 512; j += 256)
        s += projb[j] * ctw[(((size_t)j * 512 + o) * 2 + p) * 2 + q];
#pragma unroll
    for (int off = 16; off > 0; off >>= 1)
        s += __shfl_xor_sync(0xffffffffu, s, off);
    __shared__ float sm[8];
    if ((t & 31) == 0) sm[t >> 5] = s;
    __syncthreads();
    if (t == 0) {
        float S = 0.f;
#pragma unroll
        for (int i = 0; i < 8; i++) S += sm[i];
        bc[n] = 2.f * S;
    }
}

// depthwise 3x3 conv (+bias) + residual + 2x2 avgpool -> fp32 tokens
__global__ void k_dwpool(const float* __restrict__ x, const float* __restrict__ dww,
                         const float* __restrict__ dwb, float* __restrict__ t0)
{
    int bc = blockIdx.x;
    int c = bc & (Ch - 1);
    int b = bc >> 9;
    __shared__ float tile[32][33];
    const float* xp = x + (size_t)bc * 1024;
    for (int i = threadIdx.x; i < 1024; i += 256)
        tile[i >> 5][i & 31] = xp[i];
    float w[9];
#pragma unroll
    for (int i = 0; i < 9; i++) w[i] = dww[c * 9 + i];
    float bb = dwb[c];
    __syncthreads();
    int pi = threadIdx.x >> 4, pj = threadIdx.x & 15;
    float s = 0.f;
#pragma unroll
    for (int di = 0; di < 2; di++)
#pragma unroll
    for (int dj = 0; dj < 2; dj++) {
        int y = pi * 2 + di, xx = pj * 2 + dj;
        float a = bb + tile[y][xx];
#pragma unroll
        for (int u = 0; u < 3; u++)
#pragma unroll
        for (int v = 0; v < 3; v++) {
            int yy = y + u - 1, xc = xx + v - 1;
            if (yy >= 0 && yy < 32 && xc >= 0 && xc < 32)
                a += tile[yy][xc] * w[u * 3 + v];
        }
        s += a;
    }
    t0[((size_t)b * NT + pi * 16 + pj) * Ch + c] = 0.25f * s;
}

// LayerNorm over 512, fp32 in -> tf32-rounded, K-PERMUTED fp32 out
__global__ void k_ln512(const float* __restrict__ in, float* __restrict__ out,
                        const float* __restrict__ g, const float* __restrict__ beta)
{
    int row = blockIdx.x, t = threadIdx.x;
    float2 v = ((const float2*)(in + (size_t)row * Ch))[t];
    float s = v.x + v.y, q = v.x * v.x + v.y * v.y;
#pragma unroll
    for (int o = 16; o > 0; o >>= 1) {
        s += __shfl_xor_sync(0xffffffffu, s, o);
        q += __shfl_xor_sync(0xffffffffu, q, o);
    }
    __shared__ float ssm[8], qsm[8];
    if ((t & 31) == 0) { ssm[t >> 5] = s; qsm[t >> 5] = q; }
    __syncthreads();
    float S = 0.f, Q = 0.f;
#pragma unroll
    for (int i = 0; i < 8; i++) { S += ssm[i]; Q += qsm[i]; }
    float mean = S * (1.f / Ch);
    float inv = rsqrtf(Q * (1.f / Ch) - mean * mean + 1e-6f);
    float2 gg = ((const float2*)g)[t];
    float2 bb = ((const float2*)beta)[t];
    float* orow = out + (size_t)row * Ch;
    orow[kperm(2 * t)]     = rna_tf32((v.x - mean) * inv * gg.x + bb.x);
    orow[kperm(2 * t + 1)] = rna_tf32((v.y - mean) * inv * gg.y + bb.y);
}

// Fused: gather convT-GEMM row (+ct_b) -> LN -> tf32-rounded K-PERMUTED out.
// G columns are pq-major (n' = pq*512 + o) => this read is fully contiguous.
__global__ void k_scln(const float* __restrict__ G, const float* __restrict__ ctb,
                       float* __restrict__ out,
                       const float* __restrict__ g, const float* __restrict__ beta)
{
    int row = blockIdx.x, t = threadIdx.x;
    int xg = row & 31;
    int yg = (row >> 5) & 31;
    int b  = row >> 10;
    int i = yg >> 1, p = yg & 1, j = xg >> 1, q = xg & 1;
    const int pq = p * 2 + q;
    const float* gr = G + (size_t)(b * 256 + i * 16 + j) * 2048 + pq * 512;
    const int c0 = 2 * t;
    float2 cb = ((const float2*)ctb)[t];
    float2 gv = ((const float2*)gr)[t];     // contiguous, coalesced
    float2 v;
    v.x = gv.x + cb.x;
    v.y = gv.y + cb.y;

    float s = v.x + v.y, qq = v.x * v.x + v.y * v.y;
#pragma unroll
    for (int o = 16; o > 0; o >>= 1) {
        s  += __shfl_xor_sync(0xffffffffu, s, o);
        qq += __shfl_xor_sync(0xffffffffu, qq, o);
    }
    __shared__ float ssm[8], qsm[8];
    if ((t & 31) == 0) { ssm[t >> 5] = s; qsm[t >> 5] = qq; }
    __syncthreads();
    float S = 0.f, Q = 0.f;
#pragma unroll
    for (int k = 0; k < 8; k++) { S += ssm[k]; Q += qsm[k]; }
    float mean = S * (1.f / Ch);
    float inv = rsqrtf(Q * (1.f / Ch) - mean * mean + 1e-6f);
    float2 gg = ((const float2*)g)[t];
    float2 bb = ((const float2*)beta)[t];
    float* orow = out + (size_t)row * Ch;
    orow[kperm(c0)]     = rna_tf32((v.x - mean) * inv * gg.x + bb.x);
    orow[kperm(c0 + 1)] = rna_tf32((v.y - mean) * inv * gg.y + bb.y);
}

// XCA attention (fp32 in, tf32-rounded K-PERMUTED fp32 out)
__global__ void k_attn(const float* __restrict__ qkv, const float* __restrict__ mask,
                       const float* __restrict__ temp, float* __restrict__ ao)
{
    extern __shared__ float sm[];
    float* qs  = sm;            // pitch 257
    float* ks  = sm + 16448;
    float* as_ = sm + 32896;    // pitch 65
    int bh = blockIdx.x;
    int h = bh & 7, b = bh >> 3;
    int t = threadIdx.x;
    const float* base = qkv + (size_t)b * NT * 1536 + h * 64;

    for (int idx = t; idx < 64 * 256; idx += 256) {
        int d = idx & 63, n = idx >> 6;
        qs[d * 257 + n] = base[(size_t)n * 1536 + d];
        ks[d * 257 + n] = base[(size_t)n * 1536 + 512 + d];
    }
    __syncthreads();

    float tmp = temp[h];
    {
        int r = t >> 2, s4 = t & 3;
        float sq = 0.f, sk = 0.f;
        for (int n = s4 * 64; n < s4 * 64 + 64; n++) {
            float a = qs[r * 257 + n]; sq += a * a;
            float c = ks[r * 257 + n]; sk += c * c;
        }
        sq += __shfl_xor_sync(0xffffffffu, sq, 1);
        sq += __shfl_xor_sync(0xffffffffu, sq, 2);
        sk += __shfl_xor_sync(0xffffffffu, sk, 1);
        sk += __shfl_xor_sync(0xffffffffu, sk, 2);
        float qsc = tmp / fmaxf(sqrtf(sq), 1e-12f);
        float ksc = 1.f / fmaxf(sqrtf(sk), 1e-12f);
        for (int n = s4 * 64; n < s4 * 64 + 64; n++) {
            qs[r * 257 + n] *= qsc;
            ks[r * 257 + n] *= ksc;
        }
    }
    __syncthreads();

    {
        int d = t >> 2, s4 = t & 3;
        float vals[16];
#pragma unroll
        for (int i = 0; i < 16; i++) vals[i] = 0.f;
        for (int n = 0; n < 256; n++) {
            float qv = qs[d * 257 + n];
#pragma unroll
            for (int i = 0; i < 16; i++)
                vals[i] += qv * ks[(s4 * 16 + i) * 257 + n];
        }
#pragma unroll
        for (int i = 0; i < 16; i++) {
            int e = s4 * 16 + i;
            float mu = mask[(((size_t)b * 8 + h) * 64 + d) * 64 + e];
            if (mu < 0.2f) vals[i] += -1e12f;
        }
        float mx = vals[0];
#pragma unroll
        for (int i = 1; i < 16; i++) mx = fmaxf(mx, vals[i]);
        mx = fmaxf(mx, __shfl_xor_sync(0xffffffffu, mx, 1));
        mx = fmaxf(mx, __shfl_xor_sync(0xffffffffu, mx, 2));
        float sum = 0.f;
#pragma unroll
        for (int i = 0; i < 16; i++) { vals[i] = expf(vals[i] - mx); sum += vals[i]; }
        sum += __shfl_xor_sync(0xffffffffu, sum, 1);
        sum += __shfl_xor_sync(0xffffffffu, sum, 2);
        float isum = 1.f / sum;
#pragma unroll
        for (int i = 0; i < 16; i++) as_[d * 65 + s4 * 16 + i] = vals[i] * isum;
    }
    __syncthreads();

    for (int idx = t; idx < 64 * 256; idx += 256) {
        int d = idx & 63, n = idx >> 6;
        qs[d * 257 + n] = base[(size_t)n * 1536 + 1024 + d];
    }
    __syncthreads();

    {
        int d0 = (t >> 4) * 4, n0 = (t & 15) * 16;
        float acc[4][16];
#pragma unroll
        for (int i = 0; i < 4; i++)
#pragma unroll
        for (int j = 0; j < 16; j++) acc[i][j] = 0.f;
        for (int e = 0; e < 64; e++) {
            float a0 = as_[(d0 + 0) * 65 + e];
            float a1 = as_[(d0 + 1) * 65 + e];
            float a2 = as_[(d0 + 2) * 65 + e];
            float a3 = as_[(d0 + 3) * 65 + e];
#pragma unroll
            for (int j = 0; j < 16; j++) {
                float vv = qs[e * 257 + n0 + j];
                acc[0][j] += a0 * vv;
                acc[1][j] += a1 * vv;
                acc[2][j] += a2 * vv;
                acc[3][j] += a3 * vv;
            }
        }
        float* aop = ao + (size_t)b * NT * Ch + h * 64;
#pragma unroll
        for (int i = 0; i < 4; i++)
#pragma unroll
        for (int j = 0; j < 16; j++)
            aop[kperm64((size_t)(n0 + j) * Ch + d0 + i)] = rna_tf32(acc[i][j]);
    }
}

// ===========================================================================
extern "C" void kernel_launch(void* const* d_in, const int* in_sizes, int n_in,
                              void* d_out, int out_size)
{
    (void)in_sizes; (void)n_in; (void)out_size;
    const float* x     = (const float*)d_in[0];
    const float* mask  = (const float*)d_in[1];
    const float* dw_w  = (const float*)d_in[2];
    const float* dw_b  = (const float*)d_in[3];
    const float* ln1g  = (const float*)d_in[4];
    const float* ln1b  = (const float*)d_in[5];
    const float* qkvw  = (const float*)d_in[6];
    const float* qkvb  = (const float*)d_in[7];
    const float* temp  = (const float*)d_in[8];
    const float* projw = (const float*)d_in[9];
    const float* projb = (const float*)d_in[10];
    const float* ctw   = (const float*)d_in[11];
    const float* ctb   = (const float*)d_in[12];
    const float* ln2g  = (const float*)d_in[13];
    const float* ln2b  = (const float*)d_in[14];
    const float* pw1w  = (const float*)d_in[15];
    const float* pw1b  = (const float*)d_in[16];
    const float* pw2w  = (const float*)d_in[17];
    const float* pw2b  = (const float*)d_in[18];
    float* out = (float*)d_out;

    float* S = nullptr;
    cudaGetSymbolAddress((void**)&S, g_s);

    cudaFuncSetAttribute(k_attn, cudaFuncAttributeMaxDynamicSharedMemorySize, 148224);
    cudaFuncSetAttribute(gemm_tf32, cudaFuncAttributeMaxDynamicSharedMemorySize, GSMEM);

    // 0: ALL weight prep in one launch (4.19M elements)
    k_wprep<<<4194304 / 256, 256>>>(qkvw, projw, ctw, pw1w, pw2w, S);

    // 1-2: dwconv+pool, LN1
    k_dwpool<<<Bc * Ch, 256>>>(x, dw_w, dw_b, S + OFF_T0);
    k_ln512<<<M1, 256>>>(S + OFF_T0, S + OFF_TLN, ln1g, ln1b);

    // 3: qkv = LN1 @ qkv_w^T + qkv_b : [8192,1536] (feeds attention: no rnd)
    gemm_tf32<<<dim3(1536 / 128, M1 / 128), 256, GSMEM>>>(
        S + OFF_TLN, S + OFF_WQKV, qkvb, S + OFF_QKV, M1, 1536, 512, 1.f, 0, 0,
        nullptr, nullptr);

    // 4: XCA attention (tf32-rounded, K-permuted out)
    k_attn<<<Bc * NHn, 256, 148224>>>(S + OFF_QKV, mask, temp, S + OFF_AO);

    // 5: Wc[n,k] = 2 * sum_j Wct[n,j] projw[j,k]  (rnd+perm for main GEMM)
    gemm_tf32<<<dim3(512 / 128, 2048 / 128), 256, GSMEM>>>(
        S + OFF_WCT, S + OFF_PWT, nullptr, S + OFF_WC, 2048, 512, 512, 2.f, 0, 1,
        nullptr, nullptr);

    // 6: combined convT bias
    k_bc<<<2048, 256>>>(ctw, projb, S + OFF_BC);

    // 7: G = AO @ Wc^T + bc : [8192,2048], pq-major columns
    gemm_tf32<<<dim3(2048 / 128, M1 / 128), 256, GSMEM>>>(
        S + OFF_AO, S + OFF_WC, S + OFF_BC, S + OFF_G, M1, 2048, 512, 1.f, 0, 0,
        nullptr, nullptr);

    // 8: fused scatter(+ct_b) + LN2 (coalesced gather, tf32-rounded out)
    k_scln<<<M2, 256>>>(S + OFF_G, ctb, S + OFF_LN2, ln2g, ln2b);

    // 9: MLP hidden = gelu(LN2 @ pw1^T + b1) (feeds pw2 GEMM: rnd+perm)
    gemm_tf32<<<dim3(2048 / 128, M2 / 128), 256, GSMEM>>>(
        S + OFF_LN2, S + OFF_WPW1, pw1b, S + OFF_HID, M2, 2048, 512, 1.f, 1, 1,
        nullptr, nullptr);

    // 10: MLP out = hidden @ pw2^T + b2, fused final residual + NCHW transpose
    gemm_tf32<<<dim3(512 / 128, M2 / 128), 256, GSMEM>>>(
        S + OFF_HID, S + OFF_WPW2, pw2b, nullptr, M2, 512, 2048, 1.f, 0, 0,
        x, out);
}